// round 13
// baseline (speedup 1.0000x reference)
#include <cuda_runtime.h>
#include <cuda_fp16.h>
#include <math.h>
#include <stdint.h>

namespace {
constexpr int H  = 1024;
constexpr int V  = 50000;
constexpr int B  = 64;
constexpr int L  = 256;
constexpr int H3 = 3 * H;
constexpr int K2 = 2 * H;

// ---- unified fp16 GEMM (mma.sync f16 1-pass, KT=64, dynamic smem) ----
constexpr int LTJ    = 128;                 // j rows per block
constexpr int LTK    = 64;                  // k per stage
constexpr int LW_BUF = LTJ * LTK * 4;       // 32768 bytes per W stage buffer (fp32)
constexpr int L_AST  = 72;                  // A smem row stride (fp16 elements)
constexpr int LA_OFF = 2 * LW_BUF;          // 65536
constexpr int LA_BUF = 64 * L_AST * 2;      // 9216 bytes (single A buffer)
constexpr int L_SMEM = LA_OFF + LA_BUF;     // 74752 -> 3 CTAs/SM
constexpr int CST    = 132;                 // epilogue C tile stride (floats)
}

// ---------------- scratch (device globals) ----------------------------------
__device__ __align__(16) __half g_x_f16[B * H];         // relu(emb) fp16
__device__ __align__(16) __half g_h_f16[B * H];         // hidden fp16
__device__ __align__(16) __half g_cat_f16[B * K2];      // [h_new | ctx] fp16
__device__ __align__(16) float g_gi[B * H3];
__device__ __align__(16) float g_gh[B * H3];
__device__ float g_norm[B];
__device__ float g_sim[B * L];
__device__ float g_attn[B * L];

// ---------------- helpers ----------------------------------------------------
__device__ __forceinline__ float warp_sum(float v) {
#pragma unroll
    for (int o = 16; o > 0; o >>= 1) v += __shfl_xor_sync(0xFFFFFFFFu, v, o);
    return v;
}
__device__ __forceinline__ float warp_max(float v) {
#pragma unroll
    for (int o = 16; o > 0; o >>= 1) v = fmaxf(v, __shfl_xor_sync(0xFFFFFFFFu, v, o));
    return v;
}
__device__ __forceinline__ uint32_t lds2h(const __half* p) {
    return *reinterpret_cast<const uint32_t*>(p);
}
// float2 -> packed fp16x2 (RN)
__device__ __forceinline__ uint32_t f2h2(float2 f) {
    uint32_t h;
    asm("cvt.rn.f16x2.f32 %0, %1, %2;" : "=r"(h) : "f"(f.y), "f"(f.x));
    return h;
}
__device__ __forceinline__ void mma_f16(float* d, const uint32_t* a, const uint32_t* b) {
    asm volatile(
        "mma.sync.aligned.m16n8k16.row.col.f32.f16.f16.f32 "
        "{%0,%1,%2,%3}, {%4,%5,%6,%7}, {%8,%9}, {%0,%1,%2,%3};\n"
        : "+f"(d[0]), "+f"(d[1]), "+f"(d[2]), "+f"(d[3])
        : "r"(a[0]), "r"(a[1]), "r"(a[2]), "r"(a[3]), "r"(b[0]), "r"(b[1]));
}
__device__ __forceinline__ void cp16(uint32_t dst, const void* src) {
    asm volatile("cp.async.cg.shared.global [%0], [%1], 16;\n" :: "r"(dst), "l"(src));
}
__device__ __forceinline__ void cp_commit() {
    asm volatile("cp.async.commit_group;\n" ::: "memory");
}

// ---------------- K1: prep = embed gather+relu AND hid, both -> fp16 ---------
__global__ void k_prep(const int* __restrict__ ids, const float* __restrict__ emb,
                       const float* __restrict__ hid) {
    if (blockIdx.x < B) {
        int b = blockIdx.x;
        const float* src = emb + (size_t)ids[b] * H;
#pragma unroll
        for (int k = 0; k < 4; k++) {
            int h = threadIdx.x + k * 256;
            g_x_f16[b * H + h] = __float2half_rn(fmaxf(src[h], 0.0f));
        }
    } else {
        int base = (blockIdx.x - B) * 4096;
#pragma unroll
        for (int k = 0; k < 16; k++) {
            int i = base + threadIdx.x + k * 256;
            g_h_f16[i] = __float2half_rn(hid[i]);
        }
    }
}

// ---------------- unified pipelined fp16 GEMM body ---------------------------
// out[b][j] = sum_k A[b][k] * W[j][k] + bias[j]
// W fp32 [J][Kfull] streamed via cp.async (double-buffered, XOR-swizzled),
// converted to fp16 at fragment load. A fp16 [64][Kfull], SINGLE smem buffer
// (stored after the post-compute sync, regs-prefetched one stage ahead).
__device__ __forceinline__ void gemm_f16_body(
    unsigned char* dsm,
    const __half* __restrict__ A, const float* __restrict__ W,
    const float* __restrict__ bias, float* __restrict__ out,
    int K, int J, int ldo, int j0)
{
    const uint32_t smem_u32 = (uint32_t)__cvta_generic_to_shared(dsm);
    const int tid  = threadIdx.x;
    const int lane = tid & 31;
    const int wid  = tid >> 5;
    const int grp  = lane >> 2;
    const int qd   = lane & 3;
    const int jw   = (wid >> 1) * 32;
    const int bw   = (wid & 1) * 32;
    const int swz  = (grp & 3) * 8;
    const int nk   = K / LTK;

    const int wrow0 = tid >> 4;          // + i*16
    const int wcol  = (tid & 15) * 4;
    const int arow  = tid >> 2;
    const int acol  = (tid & 3) * 16;

    float acc[2][4][4];
#pragma unroll
    for (int jt = 0; jt < 2; jt++)
#pragma unroll
        for (int bt = 0; bt < 4; bt++)
#pragma unroll
            for (int q = 0; q < 4; q++) acc[jt][bt][q] = 0.0f;

    const __half* Asrc = A + (size_t)arow * K + acol;
    __half* sA = (__half*)(dsm + LA_OFF);

    // ---- prologue: A(0) -> smem; A(1) -> regs; W(0),W(1) cp.async -----------
    *(uint4*)&sA[arow * L_AST + acol]     = *(const uint4*)Asrc;
    *(uint4*)&sA[arow * L_AST + acol + 8] = *(const uint4*)(Asrc + 8);
    uint4 ra0 = *(const uint4*)(Asrc + LTK);
    uint4 ra1 = *(const uint4*)(Asrc + LTK + 8);

#pragma unroll
    for (int s = 0; s < 2; s++) {
        uint32_t wb = smem_u32 + s * LW_BUF;
#pragma unroll
        for (int i = 0; i < 8; i++) {
            int r = wrow0 + i * 16;
            int j = j0 + r; if (j > J - 1) j = J - 1;
            int c = wcol ^ ((r & 3) * 8);
            cp16(wb + (uint32_t)(r * LTK + c) * 4, &W[(size_t)j * K + s * LTK + wcol]);
        }
        cp_commit();
    }

    for (int s = 0; s < nk; s++) {
        if (s + 1 < nk) asm volatile("cp.async.wait_group 1;" ::: "memory");
        else            asm volatile("cp.async.wait_group 0;" ::: "memory");
        __syncthreads();

        uint4 na0, na1;
        if (s + 2 < nk) {
            na0 = *(const uint4*)(Asrc + (s + 2) * LTK);
            na1 = *(const uint4*)(Asrc + (s + 2) * LTK + 8);
        }

        const float* sWb = reinterpret_cast<const float*>(dsm + (s & 1) * LW_BUF);

#pragma unroll
        for (int ks = 0; ks < LTK; ks += 16) {
            const int kc = ks + qd * 2;
            const int c0 = kc ^ swz;
            const int c1 = (kc + 8) ^ swz;
            uint32_t wh[2][4];
#pragma unroll
            for (int jt = 0; jt < 2; jt++) {
                int r0 = (jw + jt * 16 + grp) * LTK;
                int r1 = r0 + 8 * LTK;
                wh[jt][0] = f2h2(*(const float2*)&sWb[r0 + c0]);
                wh[jt][1] = f2h2(*(const float2*)&sWb[r1 + c0]);
                wh[jt][2] = f2h2(*(const float2*)&sWb[r0 + c1]);
                wh[jt][3] = f2h2(*(const float2*)&sWb[r1 + c1]);
            }
            uint32_t ah[4][2];
#pragma unroll
            for (int bt = 0; bt < 4; bt++) {
                int br = bw + bt * 8 + grp;
                ah[bt][0] = lds2h(&sA[br * L_AST + kc]);
                ah[bt][1] = lds2h(&sA[br * L_AST + kc + 8]);
            }
#pragma unroll
            for (int jt = 0; jt < 2; jt++)
#pragma unroll
                for (int bt = 0; bt < 4; bt++)
                    mma_f16(acc[jt][bt], wh[jt], ah[bt]);
        }
        __syncthreads();

        if (s + 1 < nk) {   // store A(s+1) into the single A buffer
            *(uint4*)&sA[arow * L_AST + acol]     = ra0;
            *(uint4*)&sA[arow * L_AST + acol + 8] = ra1;
            ra0 = na0; ra1 = na1;
        }
        if (s + 2 < nk) {   // issue W(s+2)
            uint32_t wb = smem_u32 + ((s + 2) & 1) * LW_BUF;
#pragma unroll
            for (int i = 0; i < 8; i++) {
                int r = wrow0 + i * 16;
                int j = j0 + r; if (j > J - 1) j = J - 1;
                int c = wcol ^ ((r & 3) * 8);
                cp16(wb + (uint32_t)(r * LTK + c) * 4,
                     &W[(size_t)j * K + (s + 2) * LTK + wcol]);
            }
            cp_commit();
        }
    }

    // ---- epilogue: stage C in smem (transpose), coalesced stores ------------
    float* Ct = reinterpret_cast<float*>(dsm);
#pragma unroll
    for (int jt = 0; jt < 2; jt++)
#pragma unroll
        for (int bt = 0; bt < 4; bt++) {
            int jl = jw + jt * 16 + grp;
            int bl = bw + bt * 8 + qd * 2;
            Ct[bl * CST + jl]           = acc[jt][bt][0];
            Ct[(bl + 1) * CST + jl]     = acc[jt][bt][1];
            Ct[bl * CST + jl + 8]       = acc[jt][bt][2];
            Ct[(bl + 1) * CST + jl + 8] = acc[jt][bt][3];
        }
    __syncthreads();
#pragma unroll
    for (int p = 0; p < 8; p++) {
        int brow = (tid >> 5) + p * 8;
        int col  = lane * 4;
        float4 c = *(const float4*)&Ct[brow * CST + col];
        int j = j0 + col;
        if (j + 3 < J) {
            float4 o;
            o.x = c.x + bias[j];     o.y = c.y + bias[j + 1];
            o.z = c.z + bias[j + 2]; o.w = c.w + bias[j + 3];
            *(float4*)&out[(size_t)brow * ldo + j] = o;
        } else {
            float cv[4] = {c.x, c.y, c.z, c.w};
#pragma unroll
            for (int q = 0; q < 4; q++)
                if (j + q < J) out[(size_t)brow * ldo + j + q] = cv[q] + bias[j + q];
        }
    }
}

// ---------------- K2: GRU gate GEMMs (fp16 1-pass) ---------------------------
__global__ __launch_bounds__(256, 3) void k_gates_f16(
    const float* __restrict__ w_ih, const float* __restrict__ w_hh,
    const float* __restrict__ b_ih, const float* __restrict__ b_hh)
{
    extern __shared__ __align__(16) unsigned char dsm[];
    constexpr int NB = H3 / LTJ;   // 24 blocks per GEMM
    bool second = blockIdx.x >= NB;
    int j0 = (second ? blockIdx.x - NB : blockIdx.x) * LTJ;
    const __half* A   = second ? g_h_f16 : g_x_f16;
    const float* W    = second ? w_hh : w_ih;
    const float* bias = second ? b_hh : b_ih;
    float* out        = second ? g_gh : g_gi;
    gemm_f16_body(dsm, A, W, bias, out, H, H3, H3, j0);
}

// ---------------- K6: logits GEMM (fp16 1-pass, 3 CTAs/SM = 1 wave) ----------
__global__ __launch_bounds__(256, 3) void k_logits_f16(
    const float* __restrict__ w_out, const float* __restrict__ b_out,
    float* __restrict__ logp)
{
    extern __shared__ __align__(16) unsigned char dsm[];
    gemm_f16_body(dsm, g_cat_f16, w_out, b_out, logp, K2, V, V, blockIdx.x * LTJ);
}

// ---------------- K3: GRU gates -> h_new, norms, fp16 cat --------------------
__global__ void k_gru(const float* __restrict__ hid, float* __restrict__ hout) {
    int b = blockIdx.x;
    int j = threadIdx.x;   // blockDim = 1024
    float ir = g_gi[b * H3 + j],          hr = g_gh[b * H3 + j];
    float iz = g_gi[b * H3 + H + j],      hz = g_gh[b * H3 + H + j];
    float in_ = g_gi[b * H3 + 2 * H + j], hn = g_gh[b * H3 + 2 * H + j];
    float r = 1.0f / (1.0f + expf(-(ir + hr)));
    float z = 1.0f / (1.0f + expf(-(iz + hz)));
    float n = tanhf(in_ + r * hn);
    float hv = hid[b * H + j];
    float hnew = (1.0f - z) * n + z * hv;
    hout[b * H + j] = hnew;
    g_cat_f16[b * K2 + j] = __float2half_rn(hnew);

    __shared__ float sm[32];
    float w = warp_sum(hnew * hnew);
    if ((j & 31) == 0) sm[j >> 5] = w;
    __syncthreads();
    if (j == 0) {
        float t = 0.0f;
#pragma unroll
        for (int i = 0; i < 32; i++) t += sm[i];
        g_norm[b] = fmaxf(sqrtf(t), 1e-7f);
    }
}

// ---------------- K4: cosine sim, 8 l's per block, hnew staged in smem -------
__global__ __launch_bounds__(128) void k_sim8(
    const float* __restrict__ enc, const float* __restrict__ hnew)
{
    int b  = blockIdx.x;
    int l0 = blockIdx.y * 8;
    int lane = threadIdx.x & 31, wid = threadIdx.x >> 5;

    __shared__ __align__(16) float sh[H];
#pragma unroll
    for (int k = 0; k < 2; k++) {
        int i = threadIdx.x + k * 128;
        *(float4*)&sh[i * 4] = *(const float4*)&hnew[(size_t)b * H + i * 4];
    }
    __syncthreads();
    float nrm = g_norm[b];

    const float4* sh4 = reinterpret_cast<const float4*>(sh);
#pragma unroll
    for (int r = 0; r < 2; r++) {
        int l = l0 + wid * 2 + r;
        const float4* e4 = (const float4*)(enc + ((size_t)l * B + b) * H);
        float dot = 0.0f, sq = 0.0f;
#pragma unroll
        for (int it = 0; it < 8; it++) {
            float4 ev = e4[lane + it * 32];
            float4 hv = sh4[lane + it * 32];
            dot += ev.x * hv.x + ev.y * hv.y + ev.z * hv.z + ev.w * hv.w;
            sq  += ev.x * ev.x + ev.y * ev.y + ev.z * ev.z + ev.w * ev.w;
        }
        dot = warp_sum(dot);
        sq  = warp_sum(sq);
        if (lane == 0)
            g_sim[b * L + l] = dot / (nrm * fmaxf(sqrtf(sq), 1e-7f));
    }
}

// ---------------- K5: softmax over l ----------------------------------------
__global__ void k_softmax(float* __restrict__ aout) {
    int b = blockIdx.x, l = threadIdx.x;
    float v = g_sim[b * L + l];
    __shared__ float sm[8];
    __shared__ float bcast;
    float m = warp_max(v);
    if ((l & 31) == 0) sm[l >> 5] = m;
    __syncthreads();
    if (l == 0) {
        float t = sm[0];
#pragma unroll
        for (int i = 1; i < 8; i++) t = fmaxf(t, sm[i]);
        bcast = t;
    }
    __syncthreads();
    float e = expf(v - bcast);
    float s = warp_sum(e);
    if ((l & 31) == 0) sm[l >> 5] = s;
    __syncthreads();
    if (l == 0) {
        float t = 0.0f;
#pragma unroll
        for (int i = 0; i < 8; i++) t += sm[i];
        bcast = t;
    }
    __syncthreads();
    float a = e / bcast;
    g_attn[b * L + l] = a;
    aout[b * L + l] = a;
}

// ---------------- K5b: context vector -> fp16 cat ----------------------------
__global__ void k_ctx(const float* __restrict__ enc) {
    int b = blockIdx.y;
    int h = blockIdx.x * 256 + threadIdx.x;
    __shared__ float sa[L];
    if (threadIdx.x < L) sa[threadIdx.x] = g_attn[b * L + threadIdx.x];
    __syncthreads();
    float s0 = 0.f, s1 = 0.f, s2 = 0.f, s3 = 0.f;
#pragma unroll 4
    for (int l = 0; l < L; l += 4) {
        s0 += sa[l]     * enc[((size_t)l * B + b) * H + h];
        s1 += sa[l + 1] * enc[((size_t)(l + 1) * B + b) * H + h];
        s2 += sa[l + 2] * enc[((size_t)(l + 2) * B + b) * H + h];
        s3 += sa[l + 3] * enc[((size_t)(l + 3) * B + b) * H + h];
    }
    float s = (s0 + s1) + (s2 + s3);
    g_cat_f16[(size_t)b * K2 + H + h] = __float2half_rn(s);
}

// ---------------- K7: log_softmax over V, in place (float4) ------------------
__global__ void k_lse(float* __restrict__ logp) {
    int b = blockIdx.x;
    float* row = logp + (size_t)b * V;
    float4* row4 = reinterpret_cast<float4*>(row);
    constexpr int V4 = V / 4;
    __shared__ float sm[32];
    __shared__ float bcast;
    int tid = threadIdx.x, wid = tid >> 5, lane = tid & 31;

    float m = -3.4e38f;
    for (int v = tid; v < V4; v += 1024) {
        float4 c = row4[v];
        m = fmaxf(m, fmaxf(fmaxf(c.x, c.y), fmaxf(c.z, c.w)));
    }
    m = warp_max(m);
    if (lane == 0) sm[wid] = m;
    __syncthreads();
    if (tid == 0) {
        float t = sm[0];
#pragma unroll
        for (int i = 1; i < 32; i++) t = fmaxf(t, sm[i]);
        bcast = t;
    }
    __syncthreads();
    float bm = bcast;

    float s = 0.0f;
    for (int v = tid; v < V4; v += 1024) {
        float4 c = row4[v];
        s += expf(c.x - bm) + expf(c.y - bm) + expf(c.z - bm) + expf(c.w - bm);
    }
    s = warp_sum(s);
    if (lane == 0) sm[wid] = s;
    __syncthreads();
    if (tid == 0) {
        float t = 0.0f;
#pragma unroll
        for (int i = 0; i < 32; i++) t += sm[i];
        bcast = bm + logf(t);
    }
    __syncthreads();
    float ls = bcast;
    for (int v = tid; v < V4; v += 1024) {
        float4 c = row4[v];
        c.x -= ls; c.y -= ls; c.z -= ls; c.w -= ls;
        row4[v] = c;
    }
}

// ---------------- launch -----------------------------------------------------
extern "C" void kernel_launch(void* const* d_in, const int* in_sizes, int n_in,
                              void* d_out, int out_size) {
    const int*   ids   = (const int*)  d_in[0];
    const float* hid   = (const float*)d_in[1];
    const float* enc   = (const float*)d_in[2];
    const float* emb   = (const float*)d_in[3];
    const float* w_ih  = (const float*)d_in[4];
    const float* w_hh  = (const float*)d_in[5];
    const float* b_ih  = (const float*)d_in[6];
    const float* b_hh  = (const float*)d_in[7];
    const float* w_out = (const float*)d_in[8];
    const float* b_out = (const float*)d_in[9];

    float* out  = (float*)d_out;
    float* logp = out;                       // [B][V]
    float* hout = out + (size_t)B * V;       // [1][B][H]
    float* aout = hout + (size_t)B * H;      // [B][L]

    cudaFuncSetAttribute(k_gates_f16,
                         cudaFuncAttributeMaxDynamicSharedMemorySize, L_SMEM);
    cudaFuncSetAttribute(k_logits_f16,
                         cudaFuncAttributeMaxDynamicSharedMemorySize, L_SMEM);

    k_prep<<<B + 16, 256>>>(ids, emb, hid);
    k_gates_f16<<<2 * (H3 / LTJ), 256, L_SMEM>>>(w_ih, w_hh, b_ih, b_hh);
    k_gru<<<B, 1024>>>(hid, hout);
    dim3 gs(B, L / 8);
    k_sim8<<<gs, 128>>>(enc, hout);
    k_softmax<<<B, L>>>(aout);
    dim3 gc(H / 256, B);
    k_ctx<<<gc, 256>>>(enc);
    k_logits_f16<<<(V + LTJ - 1) / LTJ, 256, L_SMEM>>>(w_out, b_out, logp);
    k_lse<<<B, 1024>>>(logp);
}

// round 14
// speedup vs baseline: 1.1648x; 1.1648x over previous
#include <cuda_runtime.h>
#include <cuda_fp16.h>
#include <math.h>
#include <stdint.h>

namespace {
constexpr int H  = 1024;
constexpr int V  = 50000;
constexpr int B  = 64;
constexpr int L  = 256;
constexpr int H3 = 3 * H;
constexpr int K2 = 2 * H;

// ---- unified fp16 GEMM (mma.sync f16 1-pass, KT=64, dynamic smem) ----
constexpr int LTJ    = 128;                 // j rows per block
constexpr int LTK    = 64;                  // k per stage
constexpr int LW_BUF = LTJ * LTK * 4;       // 32768 bytes per W stage buffer (fp32)
constexpr int L_AST  = 72;                  // A smem row stride (fp16 elements)
constexpr int LA_OFF = 2 * LW_BUF;          // 65536
constexpr int LA_BUF = 64 * L_AST * 2;      // 9216 bytes per A buffer
constexpr int L_SMEM = LA_OFF + 2 * LA_BUF; // 83968 -> 2 CTAs/SM
constexpr int CST    = 132;                 // epilogue C tile stride (floats)
}

// ---------------- scratch (device globals) ----------------------------------
__device__ __align__(16) __half g_x_f16[B * H];         // relu(emb) fp16
__device__ __align__(16) __half g_h_f16[B * H];         // hidden fp16
__device__ __align__(16) __half g_cat_f16[B * K2];      // [h_new | ctx] fp16
__device__ __align__(16) float g_gi[B * H3];
__device__ __align__(16) float g_gh[B * H3];
__device__ float g_norm[B];
__device__ float g_sim[B * L];
__device__ float g_attn[B * L];

// ---------------- helpers ----------------------------------------------------
__device__ __forceinline__ float warp_sum(float v) {
#pragma unroll
    for (int o = 16; o > 0; o >>= 1) v += __shfl_xor_sync(0xFFFFFFFFu, v, o);
    return v;
}
__device__ __forceinline__ float warp_max(float v) {
#pragma unroll
    for (int o = 16; o > 0; o >>= 1) v = fmaxf(v, __shfl_xor_sync(0xFFFFFFFFu, v, o));
    return v;
}
__device__ __forceinline__ uint32_t lds2h(const __half* p) {
    return *reinterpret_cast<const uint32_t*>(p);
}
// float2 -> packed fp16x2 (RN)
__device__ __forceinline__ uint32_t f2h2(float2 f) {
    uint32_t h;
    asm("cvt.rn.f16x2.f32 %0, %1, %2;" : "=r"(h) : "f"(f.y), "f"(f.x));
    return h;
}
__device__ __forceinline__ void mma_f16(float* d, const uint32_t* a, const uint32_t* b) {
    asm volatile(
        "mma.sync.aligned.m16n8k16.row.col.f32.f16.f16.f32 "
        "{%0,%1,%2,%3}, {%4,%5,%6,%7}, {%8,%9}, {%0,%1,%2,%3};\n"
        : "+f"(d[0]), "+f"(d[1]), "+f"(d[2]), "+f"(d[3])
        : "r"(a[0]), "r"(a[1]), "r"(a[2]), "r"(a[3]), "r"(b[0]), "r"(b[1]));
}
__device__ __forceinline__ void cp16(uint32_t dst, const void* src) {
    asm volatile("cp.async.cg.shared.global [%0], [%1], 16;\n" :: "r"(dst), "l"(src));
}
__device__ __forceinline__ void cp_commit() {
    asm volatile("cp.async.commit_group;\n" ::: "memory");
}

// ---------------- K1: prep = embed gather+relu AND hid, both -> fp16 ---------
__global__ void k_prep(const int* __restrict__ ids, const float* __restrict__ emb,
                       const float* __restrict__ hid) {
    if (blockIdx.x < B) {
        int b = blockIdx.x;
        const float* src = emb + (size_t)ids[b] * H;
#pragma unroll
        for (int k = 0; k < 4; k++) {
            int h = threadIdx.x + k * 256;
            g_x_f16[b * H + h] = __float2half_rn(fmaxf(src[h], 0.0f));
        }
    } else {
        int base = (blockIdx.x - B) * 4096;
#pragma unroll
        for (int k = 0; k < 16; k++) {
            int i = base + threadIdx.x + k * 256;
            g_h_f16[i] = __float2half_rn(hid[i]);
        }
    }
}

// ---------------- unified pipelined fp16 GEMM body (R12 proven config) -------
// out[b][j] = sum_k A[b][k] * W[j][k] + bias[j]
// W fp32 [J][Kfull] streamed via cp.async (double-buffered, XOR-swizzled),
// converted to fp16 at fragment load. A fp16 [64][Kfull], double-buffered.
__device__ __forceinline__ void gemm_f16_body(
    unsigned char* dsm,
    const __half* __restrict__ A, const float* __restrict__ W,
    const float* __restrict__ bias, float* __restrict__ out,
    int K, int J, int ldo, int j0)
{
    const uint32_t smem_u32 = (uint32_t)__cvta_generic_to_shared(dsm);
    const int tid  = threadIdx.x;
    const int lane = tid & 31;
    const int wid  = tid >> 5;
    const int grp  = lane >> 2;
    const int qd   = lane & 3;
    const int jw   = (wid >> 1) * 32;
    const int bw   = (wid & 1) * 32;
    const int swz  = (grp & 3) * 8;
    const int nk   = K / LTK;

    const int wrow0 = tid >> 4;          // + i*16
    const int wcol  = (tid & 15) * 4;
    const int arow  = tid >> 2;
    const int acol  = (tid & 3) * 16;

    float acc[2][4][4];
#pragma unroll
    for (int jt = 0; jt < 2; jt++)
#pragma unroll
        for (int bt = 0; bt < 4; bt++)
#pragma unroll
            for (int q = 0; q < 4; q++) acc[jt][bt][q] = 0.0f;

    const __half* Asrc = A + (size_t)arow * K + acol;

    // ---- prologue: A(0) -> buf0; A(1) -> regs; W(0),W(1) cp.async -----------
    {
        __half* sA = (__half*)(dsm + LA_OFF);
        *(uint4*)&sA[arow * L_AST + acol]     = *(const uint4*)Asrc;
        *(uint4*)&sA[arow * L_AST + acol + 8] = *(const uint4*)(Asrc + 8);
    }
    uint4 ra0 = *(const uint4*)(Asrc + LTK);
    uint4 ra1 = *(const uint4*)(Asrc + LTK + 8);

#pragma unroll
    for (int s = 0; s < 2; s++) {
        uint32_t wb = smem_u32 + s * LW_BUF;
#pragma unroll
        for (int i = 0; i < 8; i++) {
            int r = wrow0 + i * 16;
            int j = j0 + r; if (j > J - 1) j = J - 1;
            int c = wcol ^ ((r & 3) * 8);
            cp16(wb + (uint32_t)(r * LTK + c) * 4, &W[(size_t)j * K + s * LTK + wcol]);
        }
        cp_commit();
    }

    for (int s = 0; s < nk; s++) {
        if (s + 1 < nk) asm volatile("cp.async.wait_group 1;" ::: "memory");
        else            asm volatile("cp.async.wait_group 0;" ::: "memory");
        __syncthreads();

        uint4 na0, na1;
        if (s + 2 < nk) {
            na0 = *(const uint4*)(Asrc + (s + 2) * LTK);
            na1 = *(const uint4*)(Asrc + (s + 2) * LTK + 8);
        }

        const float* sWb = reinterpret_cast<const float*>(dsm + (s & 1) * LW_BUF);
        const __half* sA = (const __half*)(dsm + LA_OFF + (s & 1) * LA_BUF);

#pragma unroll
        for (int ks = 0; ks < LTK; ks += 16) {
            const int kc = ks + qd * 2;
            const int c0 = kc ^ swz;
            const int c1 = (kc + 8) ^ swz;
            uint32_t wh[2][4];
#pragma unroll
            for (int jt = 0; jt < 2; jt++) {
                int r0 = (jw + jt * 16 + grp) * LTK;
                int r1 = r0 + 8 * LTK;
                wh[jt][0] = f2h2(*(const float2*)&sWb[r0 + c0]);
                wh[jt][1] = f2h2(*(const float2*)&sWb[r1 + c0]);
                wh[jt][2] = f2h2(*(const float2*)&sWb[r0 + c1]);
                wh[jt][3] = f2h2(*(const float2*)&sWb[r1 + c1]);
            }
            uint32_t ah[4][2];
#pragma unroll
            for (int bt = 0; bt < 4; bt++) {
                int br = bw + bt * 8 + grp;
                ah[bt][0] = lds2h(&sA[br * L_AST + kc]);
                ah[bt][1] = lds2h(&sA[br * L_AST + kc + 8]);
            }
#pragma unroll
            for (int jt = 0; jt < 2; jt++)
#pragma unroll
                for (int bt = 0; bt < 4; bt++)
                    mma_f16(acc[jt][bt], wh[jt], ah[bt]);
        }
        __syncthreads();

        if (s + 1 < nk) {   // store A(s+1) into the other A buffer
            __half* sAn = (__half*)(dsm + LA_OFF + ((s + 1) & 1) * LA_BUF);
            *(uint4*)&sAn[arow * L_AST + acol]     = ra0;
            *(uint4*)&sAn[arow * L_AST + acol + 8] = ra1;
            ra0 = na0; ra1 = na1;
        }
        if (s + 2 < nk) {   // issue W(s+2)
            uint32_t wb = smem_u32 + ((s + 2) & 1) * LW_BUF;
#pragma unroll
            for (int i = 0; i < 8; i++) {
                int r = wrow0 + i * 16;
                int j = j0 + r; if (j > J - 1) j = J - 1;
                int c = wcol ^ ((r & 3) * 8);
                cp16(wb + (uint32_t)(r * LTK + c) * 4,
                     &W[(size_t)j * K + (s + 2) * LTK + wcol]);
            }
            cp_commit();
        }
    }

    // ---- epilogue: stage C in smem (transpose), coalesced stores ------------
    float* Ct = reinterpret_cast<float*>(dsm);
#pragma unroll
    for (int jt = 0; jt < 2; jt++)
#pragma unroll
        for (int bt = 0; bt < 4; bt++) {
            int jl = jw + jt * 16 + grp;
            int bl = bw + bt * 8 + qd * 2;
            Ct[bl * CST + jl]           = acc[jt][bt][0];
            Ct[(bl + 1) * CST + jl]     = acc[jt][bt][1];
            Ct[bl * CST + jl + 8]       = acc[jt][bt][2];
            Ct[(bl + 1) * CST + jl + 8] = acc[jt][bt][3];
        }
    __syncthreads();
#pragma unroll
    for (int p = 0; p < 8; p++) {
        int brow = (tid >> 5) + p * 8;
        int col  = lane * 4;
        float4 c = *(const float4*)&Ct[brow * CST + col];
        int j = j0 + col;
        if (j + 3 < J) {
            float4 o;
            o.x = c.x + bias[j];     o.y = c.y + bias[j + 1];
            o.z = c.z + bias[j + 2]; o.w = c.w + bias[j + 3];
            *(float4*)&out[(size_t)brow * ldo + j] = o;
        } else {
            float cv[4] = {c.x, c.y, c.z, c.w};
#pragma unroll
            for (int q = 0; q < 4; q++)
                if (j + q < J) out[(size_t)brow * ldo + j + q] = cv[q] + bias[j + q];
        }
    }
}

// ---------------- K2: GRU gate GEMMs (fp16 1-pass) ---------------------------
__global__ __launch_bounds__(256, 2) void k_gates_f16(
    const float* __restrict__ w_ih, const float* __restrict__ w_hh,
    const float* __restrict__ b_ih, const float* __restrict__ b_hh)
{
    extern __shared__ __align__(16) unsigned char dsm[];
    constexpr int NB = H3 / LTJ;   // 24 blocks per GEMM
    bool second = blockIdx.x >= NB;
    int j0 = (second ? blockIdx.x - NB : blockIdx.x) * LTJ;
    const __half* A   = second ? g_h_f16 : g_x_f16;
    const float* W    = second ? w_hh : w_ih;
    const float* bias = second ? b_hh : b_ih;
    float* out        = second ? g_gh : g_gi;
    gemm_f16_body(dsm, A, W, bias, out, H, H3, H3, j0);
}

// ---------------- K6: logits GEMM (fp16 1-pass) ------------------------------
__global__ __launch_bounds__(256, 2) void k_logits_f16(
    const float* __restrict__ w_out, const float* __restrict__ b_out,
    float* __restrict__ logp)
{
    extern __shared__ __align__(16) unsigned char dsm[];
    gemm_f16_body(dsm, g_cat_f16, w_out, b_out, logp, K2, V, V, blockIdx.x * LTJ);
}

// ---------------- K3: GRU gates -> h_new, norms, fp16 cat --------------------
__global__ void k_gru(const float* __restrict__ hid, float* __restrict__ hout) {
    int b = blockIdx.x;
    int j = threadIdx.x;   // blockDim = 1024
    float ir = g_gi[b * H3 + j],          hr = g_gh[b * H3 + j];
    float iz = g_gi[b * H3 + H + j],      hz = g_gh[b * H3 + H + j];
    float in_ = g_gi[b * H3 + 2 * H + j], hn = g_gh[b * H3 + 2 * H + j];
    float r = 1.0f / (1.0f + expf(-(ir + hr)));
    float z = 1.0f / (1.0f + expf(-(iz + hz)));
    float n = tanhf(in_ + r * hn);
    float hv = hid[b * H + j];
    float hnew = (1.0f - z) * n + z * hv;
    hout[b * H + j] = hnew;
    g_cat_f16[b * K2 + j] = __float2half_rn(hnew);

    __shared__ float sm[32];
    float w = warp_sum(hnew * hnew);
    if ((j & 31) == 0) sm[j >> 5] = w;
    __syncthreads();
    if (j == 0) {
        float t = 0.0f;
#pragma unroll
        for (int i = 0; i < 32; i++) t += sm[i];
        g_norm[b] = fmaxf(sqrtf(t), 1e-7f);
    }
}

// ---------------- K4: cosine sim, 8 l's per block, hnew staged in smem -------
__global__ __launch_bounds__(128) void k_sim8(
    const float* __restrict__ enc, const float* __restrict__ hnew)
{
    int b  = blockIdx.x;
    int l0 = blockIdx.y * 8;
    int lane = threadIdx.x & 31, wid = threadIdx.x >> 5;

    __shared__ __align__(16) float sh[H];
#pragma unroll
    for (int k = 0; k < 2; k++) {
        int i = threadIdx.x + k * 128;
        *(float4*)&sh[i * 4] = *(const float4*)&hnew[(size_t)b * H + i * 4];
    }
    __syncthreads();
    float nrm = g_norm[b];

    const float4* sh4 = reinterpret_cast<const float4*>(sh);
#pragma unroll
    for (int r = 0; r < 2; r++) {
        int l = l0 + wid * 2 + r;
        const float4* e4 = (const float4*)(enc + ((size_t)l * B + b) * H);
        float dot = 0.0f, sq = 0.0f;
#pragma unroll
        for (int it = 0; it < 8; it++) {
            float4 ev = e4[lane + it * 32];
            float4 hv = sh4[lane + it * 32];
            dot += ev.x * hv.x + ev.y * hv.y + ev.z * hv.z + ev.w * hv.w;
            sq  += ev.x * ev.x + ev.y * ev.y + ev.z * ev.z + ev.w * ev.w;
        }
        dot = warp_sum(dot);
        sq  = warp_sum(sq);
        if (lane == 0)
            g_sim[b * L + l] = dot / (nrm * fmaxf(sqrtf(sq), 1e-7f));
    }
}

// ---------------- K5: softmax over l ----------------------------------------
__global__ void k_softmax(float* __restrict__ aout) {
    int b = blockIdx.x, l = threadIdx.x;
    float v = g_sim[b * L + l];
    __shared__ float sm[8];
    __shared__ float bcast;
    float m = warp_max(v);
    if ((l & 31) == 0) sm[l >> 5] = m;
    __syncthreads();
    if (l == 0) {
        float t = sm[0];
#pragma unroll
        for (int i = 1; i < 8; i++) t = fmaxf(t, sm[i]);
        bcast = t;
    }
    __syncthreads();
    float e = expf(v - bcast);
    float s = warp_sum(e);
    if ((l & 31) == 0) sm[l >> 5] = s;
    __syncthreads();
    if (l == 0) {
        float t = 0.0f;
#pragma unroll
        for (int i = 0; i < 8; i++) t += sm[i];
        bcast = t;
    }
    __syncthreads();
    float a = e / bcast;
    g_attn[b * L + l] = a;
    aout[b * L + l] = a;
}

// ---------------- K5b: context vector -> fp16 cat ----------------------------
__global__ void k_ctx(const float* __restrict__ enc) {
    int b = blockIdx.y;
    int h = blockIdx.x * 256 + threadIdx.x;
    __shared__ float sa[L];
    if (threadIdx.x < L) sa[threadIdx.x] = g_attn[b * L + threadIdx.x];
    __syncthreads();
    float s0 = 0.f, s1 = 0.f, s2 = 0.f, s3 = 0.f;
#pragma unroll 4
    for (int l = 0; l < L; l += 4) {
        s0 += sa[l]     * enc[((size_t)l * B + b) * H + h];
        s1 += sa[l + 1] * enc[((size_t)(l + 1) * B + b) * H + h];
        s2 += sa[l + 2] * enc[((size_t)(l + 2) * B + b) * H + h];
        s3 += sa[l + 3] * enc[((size_t)(l + 3) * B + b) * H + h];
    }
    float s = (s0 + s1) + (s2 + s3);
    g_cat_f16[(size_t)b * K2 + H + h] = __float2half_rn(s);
}

// ---------------- K7: log_softmax over V, in place (float4) ------------------
__global__ void k_lse(float* __restrict__ logp) {
    int b = blockIdx.x;
    float* row = logp + (size_t)b * V;
    float4* row4 = reinterpret_cast<float4*>(row);
    constexpr int V4 = V / 4;
    __shared__ float sm[32];
    __shared__ float bcast;
    int tid = threadIdx.x, wid = tid >> 5, lane = tid & 31;

    float m = -3.4e38f;
    for (int v = tid; v < V4; v += 1024) {
        float4 c = row4[v];
        m = fmaxf(m, fmaxf(fmaxf(c.x, c.y), fmaxf(c.z, c.w)));
    }
    m = warp_max(m);
    if (lane == 0) sm[wid] = m;
    __syncthreads();
    if (tid == 0) {
        float t = sm[0];
#pragma unroll
        for (int i = 1; i < 32; i++) t = fmaxf(t, sm[i]);
        bcast = t;
    }
    __syncthreads();
    float bm = bcast;

    float s = 0.0f;
    for (int v = tid; v < V4; v += 1024) {
        float4 c = row4[v];
        s += expf(c.x - bm) + expf(c.y - bm) + expf(c.z - bm) + expf(c.w - bm);
    }
    s = warp_sum(s);
    if (lane == 0) sm[wid] = s;
    __syncthreads();
    if (tid == 0) {
        float t = 0.0f;
#pragma unroll
        for (int i = 0; i < 32; i++) t += sm[i];
        bcast = bm + logf(t);
    }
    __syncthreads();
    float ls = bcast;
    for (int v = tid; v < V4; v += 1024) {
        float4 c = row4[v];
        c.x -= ls; c.y -= ls; c.z -= ls; c.w -= ls;
        row4[v] = c;
    }
}

// ---------------- launch -----------------------------------------------------
extern "C" void kernel_launch(void* const* d_in, const int* in_sizes, int n_in,
                              void* d_out, int out_size) {
    const int*   ids   = (const int*)  d_in[0];
    const float* hid   = (const float*)d_in[1];
    const float* enc   = (const float*)d_in[2];
    const float* emb   = (const float*)d_in[3];
    const float* w_ih  = (const float*)d_in[4];
    const float* w_hh  = (const float*)d_in[5];
    const float* b_ih  = (const float*)d_in[6];
    const float* b_hh  = (const float*)d_in[7];
    const float* w_out = (const float*)d_in[8];
    const float* b_out = (const float*)d_in[9];

    float* out  = (float*)d_out;
    float* logp = out;                       // [B][V]
    float* hout = out + (size_t)B * V;       // [1][B][H]
    float* aout = hout + (size_t)B * H;      // [B][L]

    cudaFuncSetAttribute(k_gates_f16,
                         cudaFuncAttributeMaxDynamicSharedMemorySize, L_SMEM);
    cudaFuncSetAttribute(k_logits_f16,
                         cudaFuncAttributeMaxDynamicSharedMemorySize, L_SMEM);

    k_prep<<<B + 16, 256>>>(ids, emb, hid);
    k_gates_f16<<<2 * (H3 / LTJ), 256, L_SMEM>>>(w_ih, w_hh, b_ih, b_hh);
    k_gru<<<B, 1024>>>(hid, hout);
    dim3 gs(B, L / 8);
    k_sim8<<<gs, 128>>>(enc, hout);
    k_softmax<<<B, L>>>(aout);
    dim3 gc(H / 256, B);
    k_ctx<<<gc, 256>>>(enc);
    k_logits_f16<<<(V + LTJ - 1) / LTJ, 256, L_SMEM>>>(w_out, b_out, logp);
    k_lse<<<B, 1024>>>(logp);
}

// round 15
// speedup vs baseline: 1.1916x; 1.0230x over previous
#include <cuda_runtime.h>
#include <cuda_fp16.h>
#include <math.h>
#include <stdint.h>

namespace {
constexpr int H  = 1024;
constexpr int V  = 50000;
constexpr int B  = 64;
constexpr int L  = 256;
constexpr int H3 = 3 * H;
constexpr int K2 = 2 * H;

// ---- unified fp16 GEMM (mma.sync f16 1-pass, KT=64, dynamic smem) ----
constexpr int LTJ    = 128;                 // j rows per block
constexpr int LTK    = 64;                  // k per stage
constexpr int LW_BUF = LTJ * LTK * 4;       // 32768 bytes per W stage buffer (fp32)
constexpr int L_AST  = 72;                  // A smem row stride (fp16 elements)
constexpr int LA_OFF = 2 * LW_BUF;          // 65536
constexpr int LA_BUF = 64 * L_AST * 2;      // 9216 bytes per A buffer
constexpr int L_SMEM = LA_OFF + 2 * LA_BUF; // 83968 -> 2 CTAs/SM
constexpr int CST    = 132;                 // epilogue C tile stride (floats)
}

// ---------------- scratch (device globals) ----------------------------------
__device__ __align__(16) __half g_x_f16[B * H];         // relu(emb) fp16
__device__ __align__(16) __half g_h_f16[B * H];         // hidden fp16
__device__ __align__(16) __half g_cat_f16[B * K2];      // [h_new | ctx] fp16
__device__ __align__(16) float g_gi[B * H3];
__device__ __align__(16) float g_gh[B * H3];
__device__ float g_norm[B];
__device__ float g_sim[B * L];

// ---------------- helpers ----------------------------------------------------
__device__ __forceinline__ float warp_sum(float v) {
#pragma unroll
    for (int o = 16; o > 0; o >>= 1) v += __shfl_xor_sync(0xFFFFFFFFu, v, o);
    return v;
}
__device__ __forceinline__ float warp_max(float v) {
#pragma unroll
    for (int o = 16; o > 0; o >>= 1) v = fmaxf(v, __shfl_xor_sync(0xFFFFFFFFu, v, o));
    return v;
}
__device__ __forceinline__ uint32_t lds2h(const __half* p) {
    return *reinterpret_cast<const uint32_t*>(p);
}
// float2 -> packed fp16x2 (RN)
__device__ __forceinline__ uint32_t f2h2(float2 f) {
    uint32_t h;
    asm("cvt.rn.f16x2.f32 %0, %1, %2;" : "=r"(h) : "f"(f.y), "f"(f.x));
    return h;
}
__device__ __forceinline__ void mma_f16(float* d, const uint32_t* a, const uint32_t* b) {
    asm volatile(
        "mma.sync.aligned.m16n8k16.row.col.f32.f16.f16.f32 "
        "{%0,%1,%2,%3}, {%4,%5,%6,%7}, {%8,%9}, {%0,%1,%2,%3};\n"
        : "+f"(d[0]), "+f"(d[1]), "+f"(d[2]), "+f"(d[3])
        : "r"(a[0]), "r"(a[1]), "r"(a[2]), "r"(a[3]), "r"(b[0]), "r"(b[1]));
}
__device__ __forceinline__ void cp16(uint32_t dst, const void* src) {
    asm volatile("cp.async.cg.shared.global [%0], [%1], 16;\n" :: "r"(dst), "l"(src));
}
__device__ __forceinline__ void cp_commit() {
    asm volatile("cp.async.commit_group;\n" ::: "memory");
}

// ---------------- K1: prep = embed gather+relu AND hid, both -> fp16 ---------
__global__ void k_prep(const int* __restrict__ ids, const float* __restrict__ emb,
                       const float* __restrict__ hid) {
    if (blockIdx.x < B) {
        int b = blockIdx.x;
        const float* src = emb + (size_t)ids[b] * H;
#pragma unroll
        for (int k = 0; k < 4; k++) {
            int h = threadIdx.x + k * 256;
            g_x_f16[b * H + h] = __float2half_rn(fmaxf(src[h], 0.0f));
        }
    } else {
        int base = (blockIdx.x - B) * 4096;
#pragma unroll
        for (int k = 0; k < 16; k++) {
            int i = base + threadIdx.x + k * 256;
            g_h_f16[i] = __float2half_rn(hid[i]);
        }
    }
}

// ---------------- unified pipelined fp16 GEMM body (R12 proven config) -------
// out[b][j] = sum_k A[b][k] * W[j][k] + bias[j]
// W fp32 [J][Kfull] streamed via cp.async (double-buffered, XOR-swizzled),
// converted to fp16 at fragment load. A fp16 [64][Kfull], double-buffered.
__device__ __forceinline__ void gemm_f16_body(
    unsigned char* dsm,
    const __half* __restrict__ A, const float* __restrict__ W,
    const float* __restrict__ bias, float* __restrict__ out,
    int K, int J, int ldo, int j0)
{
    const uint32_t smem_u32 = (uint32_t)__cvta_generic_to_shared(dsm);
    const int tid  = threadIdx.x;
    const int lane = tid & 31;
    const int wid  = tid >> 5;
    const int grp  = lane >> 2;
    const int qd   = lane & 3;
    const int jw   = (wid >> 1) * 32;
    const int bw   = (wid & 1) * 32;
    const int swz  = (grp & 3) * 8;
    const int nk   = K / LTK;

    const int wrow0 = tid >> 4;          // + i*16
    const int wcol  = (tid & 15) * 4;
    const int arow  = tid >> 2;
    const int acol  = (tid & 3) * 16;

    float acc[2][4][4];
#pragma unroll
    for (int jt = 0; jt < 2; jt++)
#pragma unroll
        for (int bt = 0; bt < 4; bt++)
#pragma unroll
            for (int q = 0; q < 4; q++) acc[jt][bt][q] = 0.0f;

    const __half* Asrc = A + (size_t)arow * K + acol;

    // ---- prologue: A(0) -> buf0; A(1) -> regs; W(0),W(1) cp.async -----------
    {
        __half* sA = (__half*)(dsm + LA_OFF);
        *(uint4*)&sA[arow * L_AST + acol]     = *(const uint4*)Asrc;
        *(uint4*)&sA[arow * L_AST + acol + 8] = *(const uint4*)(Asrc + 8);
    }
    uint4 ra0 = *(const uint4*)(Asrc + LTK);
    uint4 ra1 = *(const uint4*)(Asrc + LTK + 8);

#pragma unroll
    for (int s = 0; s < 2; s++) {
        uint32_t wb = smem_u32 + s * LW_BUF;
#pragma unroll
        for (int i = 0; i < 8; i++) {
            int r = wrow0 + i * 16;
            int j = j0 + r; if (j > J - 1) j = J - 1;
            int c = wcol ^ ((r & 3) * 8);
            cp16(wb + (uint32_t)(r * LTK + c) * 4, &W[(size_t)j * K + s * LTK + wcol]);
        }
        cp_commit();
    }

    for (int s = 0; s < nk; s++) {
        if (s + 1 < nk) asm volatile("cp.async.wait_group 1;" ::: "memory");
        else            asm volatile("cp.async.wait_group 0;" ::: "memory");
        __syncthreads();

        uint4 na0, na1;
        if (s + 2 < nk) {
            na0 = *(const uint4*)(Asrc + (s + 2) * LTK);
            na1 = *(const uint4*)(Asrc + (s + 2) * LTK + 8);
        }

        const float* sWb = reinterpret_cast<const float*>(dsm + (s & 1) * LW_BUF);
        const __half* sA = (const __half*)(dsm + LA_OFF + (s & 1) * LA_BUF);

#pragma unroll
        for (int ks = 0; ks < LTK; ks += 16) {
            const int kc = ks + qd * 2;
            const int c0 = kc ^ swz;
            const int c1 = (kc + 8) ^ swz;
            uint32_t wh[2][4];
#pragma unroll
            for (int jt = 0; jt < 2; jt++) {
                int r0 = (jw + jt * 16 + grp) * LTK;
                int r1 = r0 + 8 * LTK;
                wh[jt][0] = f2h2(*(const float2*)&sWb[r0 + c0]);
                wh[jt][1] = f2h2(*(const float2*)&sWb[r1 + c0]);
                wh[jt][2] = f2h2(*(const float2*)&sWb[r0 + c1]);
                wh[jt][3] = f2h2(*(const float2*)&sWb[r1 + c1]);
            }
            uint32_t ah[4][2];
#pragma unroll
            for (int bt = 0; bt < 4; bt++) {
                int br = bw + bt * 8 + grp;
                ah[bt][0] = lds2h(&sA[br * L_AST + kc]);
                ah[bt][1] = lds2h(&sA[br * L_AST + kc + 8]);
            }
#pragma unroll
            for (int jt = 0; jt < 2; jt++)
#pragma unroll
                for (int bt = 0; bt < 4; bt++)
                    mma_f16(acc[jt][bt], wh[jt], ah[bt]);
        }
        __syncthreads();

        if (s + 1 < nk) {   // store A(s+1) into the other A buffer
            __half* sAn = (__half*)(dsm + LA_OFF + ((s + 1) & 1) * LA_BUF);
            *(uint4*)&sAn[arow * L_AST + acol]     = ra0;
            *(uint4*)&sAn[arow * L_AST + acol + 8] = ra1;
            ra0 = na0; ra1 = na1;
        }
        if (s + 2 < nk) {   // issue W(s+2)
            uint32_t wb = smem_u32 + ((s + 2) & 1) * LW_BUF;
#pragma unroll
            for (int i = 0; i < 8; i++) {
                int r = wrow0 + i * 16;
                int j = j0 + r; if (j > J - 1) j = J - 1;
                int c = wcol ^ ((r & 3) * 8);
                cp16(wb + (uint32_t)(r * LTK + c) * 4,
                     &W[(size_t)j * K + (s + 2) * LTK + wcol]);
            }
            cp_commit();
        }
    }

    // ---- epilogue: stage C in smem (transpose), coalesced stores ------------
    float* Ct = reinterpret_cast<float*>(dsm);
#pragma unroll
    for (int jt = 0; jt < 2; jt++)
#pragma unroll
        for (int bt = 0; bt < 4; bt++) {
            int jl = jw + jt * 16 + grp;
            int bl = bw + bt * 8 + qd * 2;
            Ct[bl * CST + jl]           = acc[jt][bt][0];
            Ct[(bl + 1) * CST + jl]     = acc[jt][bt][1];
            Ct[bl * CST + jl + 8]       = acc[jt][bt][2];
            Ct[(bl + 1) * CST + jl + 8] = acc[jt][bt][3];
        }
    __syncthreads();
#pragma unroll
    for (int p = 0; p < 8; p++) {
        int brow = (tid >> 5) + p * 8;
        int col  = lane * 4;
        float4 c = *(const float4*)&Ct[brow * CST + col];
        int j = j0 + col;
        if (j + 3 < J) {
            float4 o;
            o.x = c.x + bias[j];     o.y = c.y + bias[j + 1];
            o.z = c.z + bias[j + 2]; o.w = c.w + bias[j + 3];
            *(float4*)&out[(size_t)brow * ldo + j] = o;
        } else {
            float cv[4] = {c.x, c.y, c.z, c.w};
#pragma unroll
            for (int q = 0; q < 4; q++)
                if (j + q < J) out[(size_t)brow * ldo + j + q] = cv[q] + bias[j + q];
        }
    }
}

// ---------------- K2: GRU gate GEMMs (fp16 1-pass) ---------------------------
__global__ __launch_bounds__(256, 2) void k_gates_f16(
    const float* __restrict__ w_ih, const float* __restrict__ w_hh,
    const float* __restrict__ b_ih, const float* __restrict__ b_hh)
{
    extern __shared__ __align__(16) unsigned char dsm[];
    constexpr int NB = H3 / LTJ;   // 24 blocks per GEMM
    bool second = blockIdx.x >= NB;
    int j0 = (second ? blockIdx.x - NB : blockIdx.x) * LTJ;
    const __half* A   = second ? g_h_f16 : g_x_f16;
    const float* W    = second ? w_hh : w_ih;
    const float* bias = second ? b_hh : b_ih;
    float* out        = second ? g_gh : g_gi;
    gemm_f16_body(dsm, A, W, bias, out, H, H3, H3, j0);
}

// ---------------- K6: logits GEMM (fp16 1-pass) ------------------------------
__global__ __launch_bounds__(256, 2) void k_logits_f16(
    const float* __restrict__ w_out, const float* __restrict__ b_out,
    float* __restrict__ logp)
{
    extern __shared__ __align__(16) unsigned char dsm[];
    gemm_f16_body(dsm, g_cat_f16, w_out, b_out, logp, K2, V, V, blockIdx.x * LTJ);
}

// ---------------- K3: GRU gates -> h_new, norms, fp16 cat --------------------
__global__ void k_gru(const float* __restrict__ hid, float* __restrict__ hout) {
    int b = blockIdx.x;
    int j = threadIdx.x;   // blockDim = 1024
    float ir = g_gi[b * H3 + j],          hr = g_gh[b * H3 + j];
    float iz = g_gi[b * H3 + H + j],      hz = g_gh[b * H3 + H + j];
    float in_ = g_gi[b * H3 + 2 * H + j], hn = g_gh[b * H3 + 2 * H + j];
    float r = 1.0f / (1.0f + expf(-(ir + hr)));
    float z = 1.0f / (1.0f + expf(-(iz + hz)));
    float n = tanhf(in_ + r * hn);
    float hv = hid[b * H + j];
    float hnew = (1.0f - z) * n + z * hv;
    hout[b * H + j] = hnew;
    g_cat_f16[b * K2 + j] = __float2half_rn(hnew);

    __shared__ float sm[32];
    float w = warp_sum(hnew * hnew);
    if ((j & 31) == 0) sm[j >> 5] = w;
    __syncthreads();
    if (j == 0) {
        float t = 0.0f;
#pragma unroll
        for (int i = 0; i < 32; i++) t += sm[i];
        g_norm[b] = fmaxf(sqrtf(t), 1e-7f);
    }
}

// ---------------- K4: cosine sim, 8 l's per block, hnew staged in smem -------
__global__ __launch_bounds__(128) void k_sim8(
    const float* __restrict__ enc, const float* __restrict__ hnew)
{
    int b  = blockIdx.x;
    int l0 = blockIdx.y * 8;
    int lane = threadIdx.x & 31, wid = threadIdx.x >> 5;

    __shared__ __align__(16) float sh[H];
#pragma unroll
    for (int k = 0; k < 2; k++) {
        int i = threadIdx.x + k * 128;
        *(float4*)&sh[i * 4] = *(const float4*)&hnew[(size_t)b * H + i * 4];
    }
    __syncthreads();
    float nrm = g_norm[b];

    const float4* sh4 = reinterpret_cast<const float4*>(sh);
#pragma unroll
    for (int r = 0; r < 2; r++) {
        int l = l0 + wid * 2 + r;
        const float4* e4 = (const float4*)(enc + ((size_t)l * B + b) * H);
        float dot = 0.0f, sq = 0.0f;
#pragma unroll
        for (int it = 0; it < 8; it++) {
            float4 ev = e4[lane + it * 32];
            float4 hv = sh4[lane + it * 32];
            dot += ev.x * hv.x + ev.y * hv.y + ev.z * hv.z + ev.w * hv.w;
            sq  += ev.x * ev.x + ev.y * ev.y + ev.z * ev.z + ev.w * ev.w;
        }
        dot = warp_sum(dot);
        sq  = warp_sum(sq);
        if (lane == 0)
            g_sim[b * L + l] = dot / (nrm * fmaxf(sqrtf(sq), 1e-7f));
    }
}

// ---------------- K5: fused softmax + context (softmax redundant per block) --
// grid (4, B), 256 threads. Each block: softmax over g_sim[b,:] into smem,
// then ctx for its H/4 chunk. Block x==0 also writes attn output.
__global__ __launch_bounds__(256) void k_ctx_sm(
    const float* __restrict__ enc, float* __restrict__ aout)
{
    int b = blockIdx.y;
    int tid = threadIdx.x, lane = tid & 31, wid = tid >> 5;
    __shared__ float sa[L];
    __shared__ float red[8];
    __shared__ float bc;

    // softmax over l (256 values, 256 threads)
    float v = g_sim[b * L + tid];
    float m = warp_max(v);
    if (lane == 0) red[wid] = m;
    __syncthreads();
    if (tid == 0) {
        float t = red[0];
#pragma unroll
        for (int i = 1; i < 8; i++) t = fmaxf(t, red[i]);
        bc = t;
    }
    __syncthreads();
    float e = expf(v - bc);
    float s = warp_sum(e);
    if (lane == 0) red[wid] = s;
    __syncthreads();
    if (tid == 0) {
        float t = 0.0f;
#pragma unroll
        for (int i = 0; i < 8; i++) t += red[i];
        bc = t;
    }
    __syncthreads();
    float a = e / bc;
    sa[tid] = a;
    if (blockIdx.x == 0) aout[b * L + tid] = a;
    __syncthreads();

    // context for h chunk
    int h = blockIdx.x * 256 + tid;
    float s0 = 0.f, s1 = 0.f, s2 = 0.f, s3 = 0.f;
#pragma unroll 4
    for (int l = 0; l < L; l += 4) {
        s0 += sa[l]     * enc[((size_t)l * B + b) * H + h];
        s1 += sa[l + 1] * enc[((size_t)(l + 1) * B + b) * H + h];
        s2 += sa[l + 2] * enc[((size_t)(l + 2) * B + b) * H + h];
        s3 += sa[l + 3] * enc[((size_t)(l + 3) * B + b) * H + h];
    }
    float sc = (s0 + s1) + (s2 + s3);
    g_cat_f16[(size_t)b * K2 + H + h] = __float2half_rn(sc);
}

// ---------------- K7: log_softmax over V, 2 passes, no max (values bounded) --
__global__ void k_lse(float* __restrict__ logp) {
    int b = blockIdx.x;
    float* row = logp + (size_t)b * V;
    float4* row4 = reinterpret_cast<float4*>(row);
    constexpr int V4 = V / 4;
    __shared__ float sm[32];
    __shared__ float bcast;
    int tid = threadIdx.x, wid = tid >> 5, lane = tid & 31;

    float s = 0.0f;
    for (int v = tid; v < V4; v += 1024) {
        float4 c = row4[v];
        s += expf(c.x) + expf(c.y) + expf(c.z) + expf(c.w);
    }
    s = warp_sum(s);
    if (lane == 0) sm[wid] = s;
    __syncthreads();
    if (tid == 0) {
        float t = 0.0f;
#pragma unroll
        for (int i = 0; i < 32; i++) t += sm[i];
        bcast = logf(t);
    }
    __syncthreads();
    float ls = bcast;
    for (int v = tid; v < V4; v += 1024) {
        float4 c = row4[v];
        c.x -= ls; c.y -= ls; c.z -= ls; c.w -= ls;
        row4[v] = c;
    }
}

// ---------------- launch -----------------------------------------------------
extern "C" void kernel_launch(void* const* d_in, const int* in_sizes, int n_in,
                              void* d_out, int out_size) {
    const int*   ids   = (const int*)  d_in[0];
    const float* hid   = (const float*)d_in[1];
    const float* enc   = (const float*)d_in[2];
    const float* emb   = (const float*)d_in[3];
    const float* w_ih  = (const float*)d_in[4];
    const float* w_hh  = (const float*)d_in[5];
    const float* b_ih  = (const float*)d_in[6];
    const float* b_hh  = (const float*)d_in[7];
    const float* w_out = (const float*)d_in[8];
    const float* b_out = (const float*)d_in[9];

    float* out  = (float*)d_out;
    float* logp = out;                       // [B][V]
    float* hout = out + (size_t)B * V;       // [1][B][H]
    float* aout = hout + (size_t)B * H;      // [B][L]

    cudaFuncSetAttribute(k_gates_f16,
                         cudaFuncAttributeMaxDynamicSharedMemorySize, L_SMEM);
    cudaFuncSetAttribute(k_logits_f16,
                         cudaFuncAttributeMaxDynamicSharedMemorySize, L_SMEM);

    k_prep<<<B + 16, 256>>>(ids, emb, hid);
    k_gates_f16<<<2 * (H3 / LTJ), 256, L_SMEM>>>(w_ih, w_hh, b_ih, b_hh);
    k_gru<<<B, 1024>>>(hid, hout);
    dim3 gs(B, L / 8);
    k_sim8<<<gs, 128>>>(enc, hout);
    dim3 gc(H / 256, B);
    k_ctx_sm<<<gc, 256>>>(enc, aout);
    k_logits_f16<<<(V + LTJ - 1) / LTJ, 256, L_SMEM>>>(w_out, b_out, logp);
    k_lse<<<B, 1024>>>(logp);
}